// round 13
// baseline (speedup 1.0000x reference)
#include <cuda_runtime.h>
#include <cuda_bf16.h>

// Problem constants
#define B 64
#define L 512
#define T 8
#define D 1024
#define C 3
#define N_HOPS 6
#define LS 8
#define LCHUNK 64
#define NATTN (B * LS)
#define CHB 64              // chain blocks (co-resident: 64 < 148 SMs)

// ---------------- device scratch ----------------
__device__ float g_P[7][4][D];          // projection chains: [k][0]=W^k wa2, [k][1+m]=W^k Wout[:,m]
__device__ float g_c[5][B][L];          // c_k[b,l] = p_k . emb_row
__device__ float g_smb[B][L];           // v_loc * (emb . wa1)
__device__ float g_vloc[B][L];
__device__ float g_vec[B][D];           // v_aspect (vec_0)
__device__ float g_aw6[N_HOPS][B][L];   // alpha*v_loc per hop
__device__ float g_cp[LS][B][6][D];     // phase-C split-L partials
__device__ float g_a[6][B][D];          // a_j = attn_out at hop j
__device__ int g_bar_count;             // static-zero; returns to 0 after each barrier
__device__ int g_bar_phase;

__device__ __forceinline__ float dot4(const float4 a, const float4 b) {
    return a.x * b.x + a.y * b.y + a.z * b.z + a.w * b.w;
}

// packed f32x2 fma: d += a*b (elementwise on 2 floats)
__device__ __forceinline__ void ffma2(unsigned long long& d, unsigned long long a,
                                      unsigned long long b) {
    asm("fma.rn.f32x2 %0, %1, %2, %0;" : "+l"(d) : "l"(a), "l"(b));
}

union F4U2 {
    float4 f;
    unsigned long long u[2];
};

// ---------------- grid barrier for CHB blocks (sense reversal) -------------------
__device__ __forceinline__ void grid_barrier64() {
    __syncthreads();
    if (threadIdx.x == 0) {
        volatile int* ph = &g_bar_phase;
        int phase = *ph;
        __threadfence();
        if (atomicAdd(&g_bar_count, 1) == CHB - 1) {
            g_bar_count = 0;
            __threadfence();
            *ph = phase ^ 1;
        } else {
            while (*ph == phase) { }
        }
        __threadfence();
    }
    __syncthreads();
}

// ---------------- reduction helpers (512-thread blocks) --------------------------
template <int NV>
__device__ __forceinline__ void block_multired(float* v, float* scratch /*16*NV*/,
                                               float* out /*NV*/, int tid) {
    int lane = tid & 31, wid = tid >> 5;
    #pragma unroll
    for (int i = 0; i < NV; i++)
        #pragma unroll
        for (int o = 16; o > 0; o >>= 1)
            v[i] += __shfl_xor_sync(0xffffffffu, v[i], o);
    if (lane == 0)
        #pragma unroll
        for (int i = 0; i < NV; i++) scratch[wid * NV + i] = v[i];
    __syncthreads();
    if (tid < NV) {
        float s = 0.f;
        #pragma unroll
        for (int w = 0; w < 16; w++) s += scratch[w * NV + tid];
        out[tid] = s;
    }
    __syncthreads();
}

__device__ __forceinline__ float block_max512(float v, float* mscr /*33*/, int tid) {
    int lane = tid & 31, wid = tid >> 5;
    #pragma unroll
    for (int o = 16; o > 0; o >>= 1)
        v = fmaxf(v, __shfl_xor_sync(0xffffffffu, v, o));
    if (lane == 0) mscr[wid] = v;
    __syncthreads();
    if (tid < 32) {
        float m = (tid < 16) ? mscr[tid] : -1e30f;
        #pragma unroll
        for (int o = 8; o > 0; o >>= 1)
            m = fmaxf(m, __shfl_xor_sync(0xffffffffu, m, o));
        if (tid == 0) mscr[32] = m;
    }
    __syncthreads();
    float r = mscr[32];
    __syncthreads();
    return r;
}

// ---------------- kernel: FUSED chain — init + 6 matvec steps, one launch --------
// grid CHB=64, 512 threads. Warp w of block b owns row (b*16+w); its 128B of W
// lives in registers across all steps. Per step, g_P[k] (16 KB) staged to smem.
__global__ void __launch_bounds__(512) chain_k3(const float* __restrict__ W,
                                                const float* __restrict__ wattn,
                                                const float* __restrict__ Wout) {
    __shared__ float4 sP[1024];       // 16 KB: g_P[k] flat (4 vectors x 256 float4)
    int tid = threadIdx.x;
    int lane = tid & 31, warp = tid >> 5;
    int row = blockIdx.x * 16 + warp;

    // cache W row slice in registers: 8 float4 = 128 B
    const float4* w4 = (const float4*)(W + (long)row * D);
    float4 w[8];
    #pragma unroll
    for (int j = 0; j < 8; j++) w[j] = w4[j * 32 + lane];

    // init g_P[0] (two elements per thread covers d = 0..1023 across 64 blocks? no:
    // use global thread id, only first 1024 threads chip-wide participate)
    int gt = blockIdx.x * 512 + tid;
    if (gt < D) {
        g_P[0][0][gt] = wattn[D + gt];
        #pragma unroll
        for (int m = 0; m < C; m++) g_P[0][1 + m][gt] = Wout[gt * C + m];
    }
    grid_barrier64();

    #pragma unroll 1
    for (int k = 0; k < 6; k++) {
        // stage g_P[k]: 1024 float4 over 512 threads
        const float4* src = (const float4*)g_P[k];
        sP[tid] = src[tid];
        sP[tid + 512] = src[tid + 512];
        __syncthreads();

        float acc[4];
        #pragma unroll
        for (int c = 0; c < 4; c++) {
            float a = 0.f;
            #pragma unroll
            for (int j = 0; j < 8; j++)
                a += dot4(w[j], sP[c * 256 + j * 32 + lane]);
            acc[c] = a;
        }
        #pragma unroll
        for (int c = 0; c < 4; c++)
            #pragma unroll
            for (int o = 16; o > 0; o >>= 1)
                acc[c] += __shfl_xor_sync(0xffffffffu, acc[c], o);
        if (lane < 4) g_P[k + 1][lane][row] = acc[lane];

        if (k < 5) grid_barrier64();
        else break;
    }
}

// ---------------- kernel: pass A v2 — smem-p, 4 rows/warp, packed fma ------------
// grid (B, L/32), 256 threads = 8 warps; warp handles 4 consecutive rows.
__global__ void __launch_bounds__(256) precomputeA_k(const int* __restrict__ ctx,
                                                     const int* __restrict__ clen,
                                                     const int* __restrict__ toff,
                                                     const float* __restrict__ emb,
                                                     const float* __restrict__ wattn) {
    __shared__ float4 sp4[6 * 256];   // 6 vectors x 1024 floats = 24 KB
    int tid = threadIdx.x;
    int b = blockIdx.x;

    #pragma unroll
    for (int i = tid; i < 6 * 256; i += 256) {
        int k = i >> 8, pos = i & 255;
        const float4* src = (k == 0) ? (const float4*)wattn
                                     : (const float4*)g_P[k - 1][0];
        sp4[i] = src[pos];
    }
    __syncthreads();

    int lane = tid & 31, warp = tid >> 5;
    int len = clen[b];
    int tofs = toff[b];
    int lbase = blockIdx.y * 32 + warp * 4;

    const float4* erow[4];
    bool valid[4];
    #pragma unroll
    for (int r = 0; r < 4; r++) {
        int l = lbase + r;
        valid[r] = (l < len);
        erow[r] = (const float4*)(emb + (long)ctx[b * L + l] * D);
    }

    unsigned long long acc2[6][4] = {};
    const float4 z4 = make_float4(0.f, 0.f, 0.f, 0.f);

    #pragma unroll
    for (int i = 0; i < 8; i++) {
        F4U2 e[4];
        #pragma unroll
        for (int r = 0; r < 4; r++)
            e[r].f = valid[r] ? erow[r][i * 32 + lane] : z4;
        #pragma unroll
        for (int k = 0; k < 6; k++) {
            F4U2 p;
            p.f = sp4[k * 256 + i * 32 + lane];
            #pragma unroll
            for (int r = 0; r < 4; r++) {
                ffma2(acc2[k][r], p.u[0], e[r].u[0]);
                ffma2(acc2[k][r], p.u[1], e[r].u[1]);
            }
        }
    }

    float s[6][4];
    #pragma unroll
    for (int k = 0; k < 6; k++)
        #pragma unroll
        for (int r = 0; r < 4; r++) {
            float2 t2 = *(float2*)&acc2[k][r];
            float v = t2.x + t2.y;
            #pragma unroll
            for (int o = 16; o > 0; o >>= 1)
                v += __shfl_xor_sync(0xffffffffu, v, o);
            s[k][r] = v;
        }

    if (lane == 0) {
        #pragma unroll
        for (int r = 0; r < 4; r++) {
            int l = lbase + r;
            float v = valid[r]
                        ? 1.0f - fabsf((float)(l - tofs)) / (float)len
                        : 0.f;
            g_vloc[b][l] = v;
            g_smb[b][l] = v * s[0][r];
            g_c[0][b][l] = s[1][r];
            g_c[1][b][l] = s[2][r];
            g_c[2][b][l] = s[3][r];
            g_c[3][b][l] = s[4][r];
            g_c[4][b][l] = s[5][r];
        }
    }
}

// ---------------- kernel: v_aspect -> g_vec --------------------------------------
__global__ void vaspect_k(const int* __restrict__ tgt,
                          const int* __restrict__ tlen,
                          const float* __restrict__ emb) {
    int b = blockIdx.x, t = threadIdx.x;
    int n = tlen[b];
    float4 acc = make_float4(0.f, 0.f, 0.f, 0.f);
    #pragma unroll
    for (int i = 0; i < T; i++) {
        if (i < n) {
            int id = tgt[b * T + i];
            float4 e = ((const float4*)(emb + (long)id * D))[t];
            acc.x += e.x; acc.y += e.y; acc.z += e.z; acc.w += e.w;
        }
    }
    float inv = 1.0f / (float)n;
    acc.x *= inv; acc.y *= inv; acc.z *= inv; acc.w *= inv;
    ((float4*)g_vec[b])[t] = acc;
}

// ---------------- kernel: scalar hop recurrence -> all aw_h -----------------------
// grid B, 512 threads (one per l)
__global__ void scalar_k(const int* __restrict__ clen,
                         const float* __restrict__ blin,
                         const float* __restrict__ battn) {
    int b = blockIdx.x, t = threadIdx.x;
    __shared__ float scr[16 * 12];
    __shared__ float res12[12];
    __shared__ float mscr[33];
    __shared__ float t_arr[6];
    __shared__ float beta[6];
    __shared__ float A[5];

    {
        float vals[12];
        int d = t * 2;
        float2 v0 = *(const float2*)&g_vec[b][d];
        float2 bl = *(const float2*)&blin[d];
        #pragma unroll
        for (int k = 0; k < 6; k++) {
            float2 p = *(const float2*)&g_P[k][0][d];
            vals[k] = p.x * v0.x + p.y * v0.y;
            vals[6 + k] = p.x * bl.x + p.y * bl.y;
        }
        block_multired<12>(vals, scr, res12, t);
        if (t < 6) { t_arr[t] = res12[t]; beta[t] = res12[6 + t]; }
        __syncthreads();
    }

    int len = clen[b];
    bool valid = t < len;
    float smb_l = g_smb[b][t];
    float vloc_l = g_vloc[b][t];
    float cv[5];
    #pragma unroll
    for (int k = 0; k < 5; k++) cv[k] = g_c[k][b][t];
    float bat = battn[0];

    for (int h = 0; h < N_HOPS; h++) {
        float s = t_arr[0];
        float sc = valid ? tanhf(smb_l + s + bat) : -1e30f;
        float mx = block_max512(sc, mscr, t);
        float e = valid ? expf(sc - mx) : 0.f;
        {
            float v1[1] = {e};
            block_multired<1>(v1, scr, res12, t);
        }
        float aw = (e / res12[0]) * vloc_l;
        g_aw6[h][b][t] = aw;

        float pv[5];
        #pragma unroll
        for (int k = 0; k < 5; k++) pv[k] = aw * cv[k];
        block_multired<5>(pv, scr, A, t);

        if (t == 0) {
            #pragma unroll
            for (int k = 0; k < 5; k++)
                t_arr[k] = A[k] + t_arr[k + 1] + beta[k];
        }
        __syncthreads();
    }
}

// ---------------- kernel: pass C — 6-way weighted sums (split L) -----------------
// grid NATTN=512 blocks, 256 threads; block=(b,ls)
__global__ void phaseC_k(const int* __restrict__ ctx,
                         const int* __restrict__ clen,
                         const float* __restrict__ emb) {
    int bid = blockIdx.x;
    int b = bid & (B - 1);
    int ls = bid >> 6;
    int tid = threadIdx.x;
    __shared__ int ids[LCHUNK];
    __shared__ float w[6][LCHUNK];

    int l0 = ls * LCHUNK;
    if (tid < LCHUNK) ids[tid] = ctx[b * L + l0 + tid];
    for (int i = tid; i < 6 * LCHUNK; i += 256) {
        int j = i >> 6, li = i & (LCHUNK - 1);
        w[j][li] = g_aw6[j][b][l0 + li];
    }
    __syncthreads();

    int len = clen[b];
    int lend = len - l0;
    if (lend > LCHUNK) lend = LCHUNK;
    if (lend < 0) lend = 0;

    float4 acc[6] = {};
    const float4* e4 = (const float4*)emb;
    #pragma unroll 4
    for (int i = 0; i < lend; i++) {
        float4 ev = e4[(long)ids[i] * 256 + tid];
        #pragma unroll
        for (int j = 0; j < 6; j++) {
            float wj = w[j][i];
            acc[j].x += wj * ev.x;
            acc[j].y += wj * ev.y;
            acc[j].z += wj * ev.z;
            acc[j].w += wj * ev.w;
        }
    }
    #pragma unroll
    for (int j = 0; j < 6; j++)
        *(float4*)&g_cp[ls][b][j][tid * 4] = acc[j];
}

// ---------------- kernel: combine phase-C partials -> g_a ------------------------
// grid 6*B, 256 threads
__global__ void combineC_k() {
    int bid = blockIdx.x;
    int b = bid & (B - 1);
    int j = bid >> 6;
    int t = threadIdx.x;
    float4 s = make_float4(0.f, 0.f, 0.f, 0.f);
    #pragma unroll
    for (int ls = 0; ls < LS; ls++) {
        float4 p = *(const float4*)&g_cp[ls][b][j][t * 4];
        s.x += p.x; s.y += p.y; s.z += p.z; s.w += p.w;
    }
    *(float4*)&g_a[j][b][t * 4] = s;
}

// ---------------- kernel: final logits -------------------------------------------
// grid B, 512 threads (float2 per thread)
__global__ void logits_k(const float* __restrict__ blin,
                         const float* __restrict__ bout,
                         float* __restrict__ out) {
    int b = blockIdx.x, t = threadIdx.x;
    __shared__ float scr[16 * 3];
    __shared__ float res[3];

    int d = t * 2;
    float2 v0 = *(const float2*)&g_vec[b][d];
    float2 bl = *(const float2*)&blin[d];

    float pm[3] = {};
    #pragma unroll
    for (int m = 0; m < C; m++) {
        #pragma unroll
        for (int j = 0; j < 6; j++) {
            float2 u = *(const float2*)&g_P[5 - j][1 + m][d];
            float2 a = *(const float2*)&g_a[j][b][d];
            pm[m] += u.x * a.x + u.y * a.y;
        }
        float2 u6 = *(const float2*)&g_P[6][1 + m][d];
        pm[m] += u6.x * v0.x + u6.y * v0.y;
        #pragma unroll
        for (int k = 0; k < 6; k++) {
            float2 uk = *(const float2*)&g_P[k][1 + m][d];
            pm[m] += uk.x * bl.x + uk.y * bl.y;
        }
    }
    block_multired<3>(pm, scr, res, t);
    if (t < C) out[b * C + t] = res[t] + bout[t];
}

// ---------------- launcher -------------------------------------------------------
extern "C" void kernel_launch(void* const* d_in, const int* in_sizes, int n_in,
                              void* d_out, int out_size) {
    const int*   ctx   = (const int*)d_in[0];
    const int*   tgt   = (const int*)d_in[1];
    const int*   clen  = (const int*)d_in[2];
    const int*   tlen  = (const int*)d_in[3];
    const int*   toff  = (const int*)d_in[4];
    const float* emb   = (const float*)d_in[5];
    const float* Wlin  = (const float*)d_in[6];
    const float* blin  = (const float*)d_in[7];
    const float* wattn = (const float*)d_in[8];
    const float* battn = (const float*)d_in[9];
    const float* Wout  = (const float*)d_in[10];
    const float* bout  = (const float*)d_in[11];
    float* out = (float*)d_out;

    chain_k3<<<CHB, 512>>>(Wlin, wattn, Wout);
    vaspect_k<<<B, 256>>>(tgt, tlen, emb);
    precomputeA_k<<<dim3(B, L / 32), 256>>>(ctx, clen, toff, emb, wattn);
    scalar_k<<<B, 512>>>(clen, blin, battn);
    phaseC_k<<<NATTN, 256>>>(ctx, clen, emb);
    combineC_k<<<6 * B, 256>>>();
    logits_k<<<B, 512>>>(blin, bout, out);
}

// round 14
// speedup vs baseline: 1.0686x; 1.0686x over previous
#include <cuda_runtime.h>
#include <cuda_bf16.h>

// Problem constants
#define B 64
#define L 512
#define T 8
#define D 1024
#define C 3
#define N_HOPS 6
#define LS 8
#define LCHUNK 64
#define NATTN (B * LS)

// ---------------- device scratch ----------------
__device__ float g_P[7][4][D];          // projection chains: [k][0]=W^k wa2, [k][1+m]=W^k Wout[:,m]
__device__ float g_c[5][B][L];          // c_k[b,l] = p_k . emb_row
__device__ float g_smb[B][L];           // v_loc * (emb . wa1)
__device__ float g_vloc[B][L];
__device__ float g_vec[B][D];           // v_aspect (vec_0)
__device__ float g_aw6[N_HOPS][B][L];   // alpha*v_loc per hop
__device__ float g_cp[LS][B][6][D];     // phase-C split-L partials
__device__ float g_a[6][B][D];          // a_j = attn_out at hop j

__device__ __forceinline__ float dot4(const float4 a, const float4 b) {
    return a.x * b.x + a.y * b.y + a.z * b.z + a.w * b.w;
}

// packed f32x2 fma: d += a*b (elementwise on 2 floats)
__device__ __forceinline__ void ffma2(unsigned long long& d, unsigned long long a,
                                      unsigned long long b) {
    asm("fma.rn.f32x2 %0, %1, %2, %0;" : "+l"(d) : "l"(a), "l"(b));
}

union F4U2 {
    float4 f;
    unsigned long long u[2];
};

// ---------------- reduction helpers (512-thread blocks) --------------------------
template <int NV>
__device__ __forceinline__ void block_multired(float* v, float* scratch /*16*NV*/,
                                               float* out /*NV*/, int tid) {
    int lane = tid & 31, wid = tid >> 5;
    #pragma unroll
    for (int i = 0; i < NV; i++)
        #pragma unroll
        for (int o = 16; o > 0; o >>= 1)
            v[i] += __shfl_xor_sync(0xffffffffu, v[i], o);
    if (lane == 0)
        #pragma unroll
        for (int i = 0; i < NV; i++) scratch[wid * NV + i] = v[i];
    __syncthreads();
    if (tid < NV) {
        float s = 0.f;
        #pragma unroll
        for (int w = 0; w < 16; w++) s += scratch[w * NV + tid];
        out[tid] = s;
    }
    __syncthreads();
}

__device__ __forceinline__ float block_max512(float v, float* mscr /*33*/, int tid) {
    int lane = tid & 31, wid = tid >> 5;
    #pragma unroll
    for (int o = 16; o > 0; o >>= 1)
        v = fmaxf(v, __shfl_xor_sync(0xffffffffu, v, o));
    if (lane == 0) mscr[wid] = v;
    __syncthreads();
    if (tid < 32) {
        float m = (tid < 16) ? mscr[tid] : -1e30f;
        #pragma unroll
        for (int o = 8; o > 0; o >>= 1)
            m = fmaxf(m, __shfl_xor_sync(0xffffffffu, m, o));
        if (tid == 0) mscr[32] = m;
    }
    __syncthreads();
    float r = mscr[32];
    __syncthreads();
    return r;
}

// ---------------- kernel: init projection chain (k=0) ----------------------------
__global__ void proj_init_k(const float* __restrict__ wattn,
                            const float* __restrict__ Wout) {
    int d = blockIdx.x * 256 + threadIdx.x;
    g_P[0][0][d] = wattn[D + d];
    #pragma unroll
    for (int m = 0; m < C; m++) g_P[0][1 + m][d] = Wout[d * C + m];
}

// ---------------- kernel: one chain step v3 — 4 rows/block, L1-dedup chain reads -
// grid 256, 256 threads. Thread (r=tid>>6, i=tid&63) covers float4 slices
// {i, i+64, i+128, i+192} of W row (4*bid + r). Threads with equal i across the
// 4 rows read IDENTICAL g_P addresses -> L1 broadcast, 4x less L2 traffic.
__global__ void __launch_bounds__(256) matvec4_k(const float* __restrict__ W, int k) {
    __shared__ float scr[8][4];
    int tid = threadIdx.x;
    int r = tid >> 6;          // row within block (0..3)
    int i = tid & 63;          // slice group
    int row = blockIdx.x * 4 + r;
    const float4* wrow = (const float4*)(W + (long)row * D);

    // 4 W loads (coalesced: consecutive lanes -> consecutive float4)
    float4 w0 = wrow[i];
    float4 w1 = wrow[i + 64];
    float4 w2 = wrow[i + 128];
    float4 w3 = wrow[i + 192];

    float acc[4];
    #pragma unroll
    for (int c = 0; c < 4; c++) {
        const float4* p4 = (const float4*)g_P[k][c];
        acc[c] = dot4(w0, p4[i]) + dot4(w1, p4[i + 64])
               + dot4(w2, p4[i + 128]) + dot4(w3, p4[i + 192]);
    }

    // reduce over the 64 threads of this row (= warps 2r, 2r+1)
    #pragma unroll
    for (int c = 0; c < 4; c++)
        #pragma unroll
        for (int o = 16; o > 0; o >>= 1)
            acc[c] += __shfl_xor_sync(0xffffffffu, acc[c], o);

    int lane = tid & 31, warp = tid >> 5;
    if (lane == 0)
        #pragma unroll
        for (int c = 0; c < 4; c++) scr[warp][c] = acc[c];
    __syncthreads();

    if (tid < 16) {
        int rr = tid >> 2, c = tid & 3;
        g_P[k + 1][c][blockIdx.x * 4 + rr] = scr[2 * rr][c] + scr[2 * rr + 1][c];
    }
}

// ---------------- kernel: pass A v2 — smem-p, 4 rows/warp, packed fma ------------
// grid (B, L/32), 256 threads = 8 warps; warp handles 4 consecutive rows.
__global__ void __launch_bounds__(256) precomputeA_k(const int* __restrict__ ctx,
                                                     const int* __restrict__ clen,
                                                     const int* __restrict__ toff,
                                                     const float* __restrict__ emb,
                                                     const float* __restrict__ wattn) {
    __shared__ float4 sp4[6 * 256];   // 6 vectors x 1024 floats = 24 KB
    int tid = threadIdx.x;
    int b = blockIdx.x;

    #pragma unroll
    for (int i = tid; i < 6 * 256; i += 256) {
        int k = i >> 8, pos = i & 255;
        const float4* src = (k == 0) ? (const float4*)wattn
                                     : (const float4*)g_P[k - 1][0];
        sp4[i] = src[pos];
    }
    __syncthreads();

    int lane = tid & 31, warp = tid >> 5;
    int len = clen[b];
    int tofs = toff[b];
    int lbase = blockIdx.y * 32 + warp * 4;

    const float4* erow[4];
    bool valid[4];
    #pragma unroll
    for (int r = 0; r < 4; r++) {
        int l = lbase + r;
        valid[r] = (l < len);
        erow[r] = (const float4*)(emb + (long)ctx[b * L + l] * D);
    }

    unsigned long long acc2[6][4] = {};
    const float4 z4 = make_float4(0.f, 0.f, 0.f, 0.f);

    #pragma unroll
    for (int i = 0; i < 8; i++) {
        F4U2 e[4];
        #pragma unroll
        for (int r = 0; r < 4; r++)
            e[r].f = valid[r] ? erow[r][i * 32 + lane] : z4;
        #pragma unroll
        for (int k = 0; k < 6; k++) {
            F4U2 p;
            p.f = sp4[k * 256 + i * 32 + lane];
            #pragma unroll
            for (int r = 0; r < 4; r++) {
                ffma2(acc2[k][r], p.u[0], e[r].u[0]);
                ffma2(acc2[k][r], p.u[1], e[r].u[1]);
            }
        }
    }

    float s[6][4];
    #pragma unroll
    for (int k = 0; k < 6; k++)
        #pragma unroll
        for (int r = 0; r < 4; r++) {
            float2 t2 = *(float2*)&acc2[k][r];
            float v = t2.x + t2.y;
            #pragma unroll
            for (int o = 16; o > 0; o >>= 1)
                v += __shfl_xor_sync(0xffffffffu, v, o);
            s[k][r] = v;
        }

    if (lane == 0) {
        #pragma unroll
        for (int r = 0; r < 4; r++) {
            int l = lbase + r;
            float v = valid[r]
                        ? 1.0f - fabsf((float)(l - tofs)) / (float)len
                        : 0.f;
            g_vloc[b][l] = v;
            g_smb[b][l] = v * s[0][r];
            g_c[0][b][l] = s[1][r];
            g_c[1][b][l] = s[2][r];
            g_c[2][b][l] = s[3][r];
            g_c[3][b][l] = s[4][r];
            g_c[4][b][l] = s[5][r];
        }
    }
}

// ---------------- kernel: v_aspect -> g_vec --------------------------------------
__global__ void vaspect_k(const int* __restrict__ tgt,
                          const int* __restrict__ tlen,
                          const float* __restrict__ emb) {
    int b = blockIdx.x, t = threadIdx.x;
    int n = tlen[b];
    float4 acc = make_float4(0.f, 0.f, 0.f, 0.f);
    #pragma unroll
    for (int i = 0; i < T; i++) {
        if (i < n) {
            int id = tgt[b * T + i];
            float4 e = ((const float4*)(emb + (long)id * D))[t];
            acc.x += e.x; acc.y += e.y; acc.z += e.z; acc.w += e.w;
        }
    }
    float inv = 1.0f / (float)n;
    acc.x *= inv; acc.y *= inv; acc.z *= inv; acc.w *= inv;
    ((float4*)g_vec[b])[t] = acc;
}

// ---------------- kernel: scalar hop recurrence v2 -> all aw_h --------------------
// grid B, 512 threads (one per l). Per hop: max-reduce + ONE multired<6>.
// A_k = (sum e*vloc*c_k) / (sum e); aw = e*vloc/(sum e).
__global__ void scalar_k(const int* __restrict__ clen,
                         const float* __restrict__ blin,
                         const float* __restrict__ battn) {
    int b = blockIdx.x, t = threadIdx.x;
    __shared__ float scr[16 * 12];
    __shared__ float res12[12];
    __shared__ float mscr[33];
    __shared__ float t_arr[6];
    __shared__ float beta[6];

    {
        float vals[12];
        int d = t * 2;
        float2 v0 = *(const float2*)&g_vec[b][d];
        float2 bl = *(const float2*)&blin[d];
        #pragma unroll
        for (int k = 0; k < 6; k++) {
            float2 p = *(const float2*)&g_P[k][0][d];
            vals[k] = p.x * v0.x + p.y * v0.y;
            vals[6 + k] = p.x * bl.x + p.y * bl.y;
        }
        block_multired<12>(vals, scr, res12, t);
        if (t < 6) { t_arr[t] = res12[t]; beta[t] = res12[6 + t]; }
        __syncthreads();
    }

    int len = clen[b];
    bool valid = t < len;
    float smb_l = g_smb[b][t];
    float vloc_l = g_vloc[b][t];
    float cv[5];
    #pragma unroll
    for (int k = 0; k < 5; k++) cv[k] = g_c[k][b][t];
    float bat = battn[0];

    for (int h = 0; h < N_HOPS; h++) {
        float s = t_arr[0];
        float sc = valid ? tanhf(smb_l + s + bat) : -1e30f;
        float mx = block_max512(sc, mscr, t);
        float e = valid ? expf(sc - mx) : 0.f;
        float ev = e * vloc_l;

        float vals[6];
        vals[0] = e;
        #pragma unroll
        for (int k = 0; k < 5; k++) vals[1 + k] = ev * cv[k];
        block_multired<6>(vals, scr, res12, t);

        float inv_se = 1.0f / res12[0];
        g_aw6[h][b][t] = ev * inv_se;

        if (t == 0) {
            #pragma unroll
            for (int k = 0; k < 5; k++)       // ascending: reads t_arr[k+1] pre-update
                t_arr[k] = res12[1 + k] * inv_se + t_arr[k + 1] + beta[k];
        }
        __syncthreads();
    }
}

// ---------------- kernel: pass C — 6-way weighted sums (split L) -----------------
// grid NATTN=512 blocks, 256 threads; block=(b,ls)
__global__ void phaseC_k(const int* __restrict__ ctx,
                         const int* __restrict__ clen,
                         const float* __restrict__ emb) {
    int bid = blockIdx.x;
    int b = bid & (B - 1);
    int ls = bid >> 6;
    int tid = threadIdx.x;
    __shared__ int ids[LCHUNK];
    __shared__ float w[6][LCHUNK];

    int l0 = ls * LCHUNK;
    if (tid < LCHUNK) ids[tid] = ctx[b * L + l0 + tid];
    for (int i = tid; i < 6 * LCHUNK; i += 256) {
        int j = i >> 6, li = i & (LCHUNK - 1);
        w[j][li] = g_aw6[j][b][l0 + li];
    }
    __syncthreads();

    int len = clen[b];
    int lend = len - l0;
    if (lend > LCHUNK) lend = LCHUNK;
    if (lend < 0) lend = 0;

    float4 acc[6] = {};
    const float4* e4 = (const float4*)emb;
    #pragma unroll 4
    for (int i = 0; i < lend; i++) {
        float4 ev = e4[(long)ids[i] * 256 + tid];
        #pragma unroll
        for (int j = 0; j < 6; j++) {
            float wj = w[j][i];
            acc[j].x += wj * ev.x;
            acc[j].y += wj * ev.y;
            acc[j].z += wj * ev.z;
            acc[j].w += wj * ev.w;
        }
    }
    #pragma unroll
    for (int j = 0; j < 6; j++)
        *(float4*)&g_cp[ls][b][j][tid * 4] = acc[j];
}

// ---------------- kernel: combine phase-C partials -> g_a ------------------------
// grid 6*B, 256 threads
__global__ void combineC_k() {
    int bid = blockIdx.x;
    int b = bid & (B - 1);
    int j = bid >> 6;
    int t = threadIdx.x;
    float4 s = make_float4(0.f, 0.f, 0.f, 0.f);
    #pragma unroll
    for (int ls = 0; ls < LS; ls++) {
        float4 p = *(const float4*)&g_cp[ls][b][j][t * 4];
        s.x += p.x; s.y += p.y; s.z += p.z; s.w += p.w;
    }
    *(float4*)&g_a[j][b][t * 4] = s;
}

// ---------------- kernel: final logits -------------------------------------------
// grid B, 512 threads (float2 per thread)
__global__ void logits_k(const float* __restrict__ blin,
                         const float* __restrict__ bout,
                         float* __restrict__ out) {
    int b = blockIdx.x, t = threadIdx.x;
    __shared__ float scr[16 * 3];
    __shared__ float res[3];

    int d = t * 2;
    float2 v0 = *(const float2*)&g_vec[b][d];
    float2 bl = *(const float2*)&blin[d];

    float pm[3] = {};
    #pragma unroll
    for (int m = 0; m < C; m++) {
        #pragma unroll
        for (int j = 0; j < 6; j++) {
            float2 u = *(const float2*)&g_P[5 - j][1 + m][d];
            float2 a = *(const float2*)&g_a[j][b][d];
            pm[m] += u.x * a.x + u.y * a.y;
        }
        float2 u6 = *(const float2*)&g_P[6][1 + m][d];
        pm[m] += u6.x * v0.x + u6.y * v0.y;
        #pragma unroll
        for (int k = 0; k < 6; k++) {
            float2 uk = *(const float2*)&g_P[k][1 + m][d];
            pm[m] += uk.x * bl.x + uk.y * bl.y;
        }
    }
    block_multired<3>(pm, scr, res, t);
    if (t < C) out[b * C + t] = res[t] + bout[t];
}

// ---------------- launcher -------------------------------------------------------
extern "C" void kernel_launch(void* const* d_in, const int* in_sizes, int n_in,
                              void* d_out, int out_size) {
    const int*   ctx   = (const int*)d_in[0];
    const int*   tgt   = (const int*)d_in[1];
    const int*   clen  = (const int*)d_in[2];
    const int*   tlen  = (const int*)d_in[3];
    const int*   toff  = (const int*)d_in[4];
    const float* emb   = (const float*)d_in[5];
    const float* Wlin  = (const float*)d_in[6];
    const float* blin  = (const float*)d_in[7];
    const float* wattn = (const float*)d_in[8];
    const float* battn = (const float*)d_in[9];
    const float* Wout  = (const float*)d_in[10];
    const float* bout  = (const float*)d_in[11];
    float* out = (float*)d_out;

    proj_init_k<<<4, 256>>>(wattn, Wout);
    for (int k = 0; k < 6; k++)
        matvec4_k<<<256, 256>>>(Wlin, k);

    vaspect_k<<<B, 256>>>(tgt, tlen, emb);
    precomputeA_k<<<dim3(B, L / 32), 256>>>(ctx, clen, toff, emb, wattn);
    scalar_k<<<B, 512>>>(clen, blin, battn);
    phaseC_k<<<NATTN, 256>>>(ctx, clen, emb);
    combineC_k<<<6 * B, 256>>>();
    logits_k<<<B, 512>>>(blin, bout, out);
}

// round 15
// speedup vs baseline: 1.1220x; 1.0499x over previous
#include <cuda_runtime.h>
#include <cuda_bf16.h>

// Problem constants
#define B 64
#define L 512
#define T 8
#define D 1024
#define C 3
#define N_HOPS 6
#define LS 8
#define LCHUNK 64
#define NATTN (B * LS)
#define MVB 256            // matvec blocks per step

// ---------------- device scratch ----------------
__device__ float g_P[7][4][D];          // projection chains: [k][0]=W^k wa2, [k][1+m]=W^k Wout[:,m]
__device__ float g_c[5][B][L];          // c_k[b,l] = p_k . emb_row
__device__ float g_smb[B][L];           // v_loc * (emb . wa1)
__device__ float g_vloc[B][L];
__device__ float g_vec[B][D];           // v_aspect (vec_0)
__device__ float g_aw6[N_HOPS][B][L];   // alpha*v_loc per hop
__device__ float g_cp[LS][B][6][D];     // phase-C split-L partials
__device__ float g_a[6][B][D];          // a_j = attn_out at hop j

__device__ __forceinline__ float dot4(const float4 a, const float4 b) {
    return a.x * b.x + a.y * b.y + a.z * b.z + a.w * b.w;
}

__device__ __forceinline__ void ffma2(unsigned long long& d, unsigned long long a,
                                      unsigned long long b) {
    asm("fma.rn.f32x2 %0, %1, %2, %0;" : "+l"(d) : "l"(a), "l"(b));
}

union F4U2 {
    float4 f;
    unsigned long long u[2];
};

// ---------------- reduction helper (512-thread blocks) ---------------------------
template <int NV>
__device__ __forceinline__ void block_multired(float* v, float* scratch /*16*NV*/,
                                               float* out /*NV*/, int tid) {
    int lane = tid & 31, wid = tid >> 5;
    #pragma unroll
    for (int i = 0; i < NV; i++)
        #pragma unroll
        for (int o = 16; o > 0; o >>= 1)
            v[i] += __shfl_xor_sync(0xffffffffu, v[i], o);
    if (lane == 0)
        #pragma unroll
        for (int i = 0; i < NV; i++) scratch[wid * NV + i] = v[i];
    __syncthreads();
    if (tid < NV) {
        float s = 0.f;
        #pragma unroll
        for (int w = 0; w < 16; w++) s += scratch[w * NV + tid];
        out[tid] = s;
    }
    __syncthreads();
}

// ---------------- matvec step body (R14 v3: 4 rows/block) ------------------------
// tid-layout: r=tid>>6 row-in-block, i=tid&63 slice; scr is 32 floats of smem.
__device__ __forceinline__ void matvec_role(const float* __restrict__ W, int k,
                                            int vbid, int tid, float (*scr)[4]) {
    int r = tid >> 6;
    int i = tid & 63;
    int row = vbid * 4 + r;
    const float4* wrow = (const float4*)(W + (long)row * D);

    float4 w0 = wrow[i];
    float4 w1 = wrow[i + 64];
    float4 w2 = wrow[i + 128];
    float4 w3 = wrow[i + 192];

    float acc[4];
    #pragma unroll
    for (int c = 0; c < 4; c++) {
        const float4* p4 = (const float4*)g_P[k][c];
        acc[c] = dot4(w0, p4[i]) + dot4(w1, p4[i + 64])
               + dot4(w2, p4[i + 128]) + dot4(w3, p4[i + 192]);
    }

    #pragma unroll
    for (int c = 0; c < 4; c++)
        #pragma unroll
        for (int o = 16; o > 0; o >>= 1)
            acc[c] += __shfl_xor_sync(0xffffffffu, acc[c], o);

    int lane = tid & 31, warp = tid >> 5;
    if (lane == 0)
        #pragma unroll
        for (int c = 0; c < 4; c++) scr[warp][c] = acc[c];
    __syncthreads();

    if (tid < 16) {
        int rr = tid >> 2, c = tid & 3;
        g_P[k + 1][c][vbid * 4 + rr] = scr[2 * rr][c] + scr[2 * rr + 1][c];
    }
}

// ---------------- kernel: init projection chain (k=0) ----------------------------
__global__ void proj_init_k(const float* __restrict__ wattn,
                            const float* __restrict__ Wout) {
    int d = blockIdx.x * 256 + threadIdx.x;
    g_P[0][0][d] = wattn[D + d];
    #pragma unroll
    for (int m = 0; m < C; m++) g_P[0][1 + m][d] = Wout[d * C + m];
}

// ---------------- kernel: standalone chain step (k=0..3) -------------------------
__global__ void __launch_bounds__(256) matvec4_k(const float* __restrict__ W, int k) {
    __shared__ float scr[8][4];
    matvec_role(W, k, blockIdx.x, threadIdx.x, scr);
}

// ---------------- kernel: FUSED vaspect + chain step k=4 -------------------------
// grid MVB+B = 320, 256 threads. bid<MVB: matvec role; else vaspect for b=bid-MVB.
__global__ void __launch_bounds__(256) vaspect_f_k(const int* __restrict__ tgt,
                                                   const int* __restrict__ tlen,
                                                   const float* __restrict__ emb,
                                                   const float* __restrict__ W) {
    __shared__ float scr[8][4];
    int bid = blockIdx.x;
    int t = threadIdx.x;
    if (bid < MVB) {
        matvec_role(W, 4, bid, t, scr);
        return;
    }
    int b = bid - MVB;
    int n = tlen[b];
    float4 acc = make_float4(0.f, 0.f, 0.f, 0.f);
    #pragma unroll
    for (int i = 0; i < T; i++) {
        if (i < n) {
            int id = tgt[b * T + i];
            float4 e = ((const float4*)(emb + (long)id * D))[t];
            acc.x += e.x; acc.y += e.y; acc.z += e.z; acc.w += e.w;
        }
    }
    float inv = 1.0f / (float)n;
    acc.x *= inv; acc.y *= inv; acc.z *= inv; acc.w *= inv;
    ((float4*)g_vec[b])[t] = acc;
}

// ---------------- kernel: FUSED pass A + chain step k=5 --------------------------
// grid MVB + B*16 = 1280, 256 threads. bid<MVB: matvec role (uses g_P[5] from the
// vaspect launch); else preA block (b, ly) = ((bid-MVB)&63, (bid-MVB)>>6).
__global__ void __launch_bounds__(256) preA_f_k(const int* __restrict__ ctx,
                                                const int* __restrict__ clen,
                                                const int* __restrict__ toff,
                                                const float* __restrict__ emb,
                                                const float* __restrict__ wattn,
                                                const float* __restrict__ W) {
    __shared__ float4 sp4[6 * 256];   // 24 KB; matvec role reuses the front as scr
    int tid = threadIdx.x;
    int bid = blockIdx.x;

    if (bid < MVB) {
        matvec_role(W, 5, bid, tid, (float(*)[4])sp4);
        return;
    }
    int idx = bid - MVB;
    int b = idx & 63;
    int ly = idx >> 6;

    #pragma unroll
    for (int i = tid; i < 6 * 256; i += 256) {
        int k = i >> 8, pos = i & 255;
        const float4* src = (k == 0) ? (const float4*)wattn
                                     : (const float4*)g_P[k - 1][0];
        sp4[i] = src[pos];
    }
    __syncthreads();

    int lane = tid & 31, warp = tid >> 5;
    int len = clen[b];
    int tofs = toff[b];
    int lbase = ly * 32 + warp * 4;

    const float4* erow[4];
    bool valid[4];
    #pragma unroll
    for (int r = 0; r < 4; r++) {
        int l = lbase + r;
        valid[r] = (l < len);
        erow[r] = (const float4*)(emb + (long)ctx[b * L + l] * D);
    }

    unsigned long long acc2[6][4] = {};
    const float4 z4 = make_float4(0.f, 0.f, 0.f, 0.f);

    #pragma unroll
    for (int i = 0; i < 8; i++) {
        F4U2 e[4];
        #pragma unroll
        for (int r = 0; r < 4; r++)
            e[r].f = valid[r] ? erow[r][i * 32 + lane] : z4;
        #pragma unroll
        for (int k = 0; k < 6; k++) {
            F4U2 p;
            p.f = sp4[k * 256 + i * 32 + lane];
            #pragma unroll
            for (int r = 0; r < 4; r++) {
                ffma2(acc2[k][r], p.u[0], e[r].u[0]);
                ffma2(acc2[k][r], p.u[1], e[r].u[1]);
            }
        }
    }

    float s[6][4];
    #pragma unroll
    for (int k = 0; k < 6; k++)
        #pragma unroll
        for (int r = 0; r < 4; r++) {
            float2 t2 = *(float2*)&acc2[k][r];
            float v = t2.x + t2.y;
            #pragma unroll
            for (int o = 16; o > 0; o >>= 1)
                v += __shfl_xor_sync(0xffffffffu, v, o);
            s[k][r] = v;
        }

    if (lane == 0) {
        #pragma unroll
        for (int r = 0; r < 4; r++) {
            int l = lbase + r;
            float v = valid[r]
                        ? 1.0f - fabsf((float)(l - tofs)) / (float)len
                        : 0.f;
            g_vloc[b][l] = v;
            g_smb[b][l] = v * s[0][r];
            g_c[0][b][l] = s[1][r];
            g_c[1][b][l] = s[2][r];
            g_c[2][b][l] = s[3][r];
            g_c[3][b][l] = s[4][r];
            g_c[4][b][l] = s[5][r];
        }
    }
}

// ---------------- kernel: scalar hop recurrence v3 (no max reduce) ----------------
// tanh scores are in [-1,1] -> exp needs no max subtraction; masked lanes e=0.
__global__ void scalar_k(const int* __restrict__ clen,
                         const float* __restrict__ blin,
                         const float* __restrict__ battn) {
    int b = blockIdx.x, t = threadIdx.x;
    __shared__ float scr[16 * 12];
    __shared__ float res12[12];
    __shared__ float t_arr[6];
    __shared__ float beta[6];

    {
        float vals[12];
        int d = t * 2;
        float2 v0 = *(const float2*)&g_vec[b][d];
        float2 bl = *(const float2*)&blin[d];
        #pragma unroll
        for (int k = 0; k < 6; k++) {
            float2 p = *(const float2*)&g_P[k][0][d];
            vals[k] = p.x * v0.x + p.y * v0.y;
            vals[6 + k] = p.x * bl.x + p.y * bl.y;
        }
        block_multired<12>(vals, scr, res12, t);
        if (t < 6) { t_arr[t] = res12[t]; beta[t] = res12[6 + t]; }
        __syncthreads();
    }

    int len = clen[b];
    bool valid = t < len;
    float smb_l = g_smb[b][t];
    float vloc_l = g_vloc[b][t];
    float cv[5];
    #pragma unroll
    for (int k = 0; k < 5; k++) cv[k] = g_c[k][b][t];
    float bat = battn[0];

    for (int h = 0; h < N_HOPS; h++) {
        float s = t_arr[0];
        float e = valid ? expf(tanhf(smb_l + s + bat)) : 0.f;
        float ev = e * vloc_l;

        float vals[6];
        vals[0] = e;
        #pragma unroll
        for (int k = 0; k < 5; k++) vals[1 + k] = ev * cv[k];
        block_multired<6>(vals, scr, res12, t);

        float inv_se = 1.0f / res12[0];
        g_aw6[h][b][t] = ev * inv_se;

        if (t == 0) {
            #pragma unroll
            for (int k = 0; k < 5; k++)       // ascending: reads t_arr[k+1] pre-update
                t_arr[k] = res12[1 + k] * inv_se + t_arr[k + 1] + beta[k];
        }
        __syncthreads();
    }
}

// ---------------- kernel: pass C — 6-way weighted sums (split L) -----------------
__global__ void phaseC_k(const int* __restrict__ ctx,
                         const int* __restrict__ clen,
                         const float* __restrict__ emb) {
    int bid = blockIdx.x;
    int b = bid & (B - 1);
    int ls = bid >> 6;
    int tid = threadIdx.x;
    __shared__ int ids[LCHUNK];
    __shared__ float w[6][LCHUNK];

    int l0 = ls * LCHUNK;
    if (tid < LCHUNK) ids[tid] = ctx[b * L + l0 + tid];
    for (int i = tid; i < 6 * LCHUNK; i += 256) {
        int j = i >> 6, li = i & (LCHUNK - 1);
        w[j][li] = g_aw6[j][b][l0 + li];
    }
    __syncthreads();

    int len = clen[b];
    int lend = len - l0;
    if (lend > LCHUNK) lend = LCHUNK;
    if (lend < 0) lend = 0;

    float4 acc[6] = {};
    const float4* e4 = (const float4*)emb;
    #pragma unroll 4
    for (int i = 0; i < lend; i++) {
        float4 ev = e4[(long)ids[i] * 256 + tid];
        #pragma unroll
        for (int j = 0; j < 6; j++) {
            float wj = w[j][i];
            acc[j].x += wj * ev.x;
            acc[j].y += wj * ev.y;
            acc[j].z += wj * ev.z;
            acc[j].w += wj * ev.w;
        }
    }
    #pragma unroll
    for (int j = 0; j < 6; j++)
        *(float4*)&g_cp[ls][b][j][tid * 4] = acc[j];
}

// ---------------- kernel: combine phase-C partials -> g_a ------------------------
__global__ void combineC_k() {
    int bid = blockIdx.x;
    int b = bid & (B - 1);
    int j = bid >> 6;
    int t = threadIdx.x;
    float4 s = make_float4(0.f, 0.f, 0.f, 0.f);
    #pragma unroll
    for (int ls = 0; ls < LS; ls++) {
        float4 p = *(const float4*)&g_cp[ls][b][j][t * 4];
        s.x += p.x; s.y += p.y; s.z += p.z; s.w += p.w;
    }
    *(float4*)&g_a[j][b][t * 4] = s;
}

// ---------------- kernel: final logits -------------------------------------------
__global__ void logits_k(const float* __restrict__ blin,
                         const float* __restrict__ bout,
                         float* __restrict__ out) {
    int b = blockIdx.x, t = threadIdx.x;
    __shared__ float scr[16 * 3];
    __shared__ float res[3];

    int d = t * 2;
    float2 v0 = *(const float2*)&g_vec[b][d];
    float2 bl = *(const float2*)&blin[d];

    float pm[3] = {};
    #pragma unroll
    for (int m = 0; m < C; m++) {
        #pragma unroll
        for (int j = 0; j < 6; j++) {
            float2 u = *(const float2*)&g_P[5 - j][1 + m][d];
            float2 a = *(const float2*)&g_a[j][b][d];
            pm[m] += u.x * a.x + u.y * a.y;
        }
        float2 u6 = *(const float2*)&g_P[6][1 + m][d];
        pm[m] += u6.x * v0.x + u6.y * v0.y;
        #pragma unroll
        for (int k = 0; k < 6; k++) {
            float2 uk = *(const float2*)&g_P[k][1 + m][d];
            pm[m] += uk.x * bl.x + uk.y * bl.y;
        }
    }
    block_multired<3>(pm, scr, res, t);
    if (t < C) out[b * C + t] = res[t] + bout[t];
}

// ---------------- launcher -------------------------------------------------------
extern "C" void kernel_launch(void* const* d_in, const int* in_sizes, int n_in,
                              void* d_out, int out_size) {
    const int*   ctx   = (const int*)d_in[0];
    const int*   tgt   = (const int*)d_in[1];
    const int*   clen  = (const int*)d_in[2];
    const int*   tlen  = (const int*)d_in[3];
    const int*   toff  = (const int*)d_in[4];
    const float* emb   = (const float*)d_in[5];
    const float* Wlin  = (const float*)d_in[6];
    const float* blin  = (const float*)d_in[7];
    const float* wattn = (const float*)d_in[8];
    const float* battn = (const float*)d_in[9];
    const float* Wout  = (const float*)d_in[10];
    const float* bout  = (const float*)d_in[11];
    float* out = (float*)d_out;

    proj_init_k<<<4, 256>>>(wattn, Wout);
    for (int k = 0; k < 4; k++)
        matvec4_k<<<MVB, 256>>>(Wlin, k);

    vaspect_f_k<<<MVB + B, 256>>>(tgt, tlen, emb, Wlin);          // + chain k=4
    preA_f_k<<<MVB + B * 16, 256>>>(ctx, clen, toff, emb, wattn, Wlin); // + chain k=5
    scalar_k<<<B, 512>>>(clen, blin, battn);
    phaseC_k<<<NATTN, 256>>>(ctx, clen, emb);
    combineC_k<<<6 * B, 256>>>();
    logits_k<<<B, 512>>>(blin, bout, out);
}